// round 3
// baseline (speedup 1.0000x reference)
#include <cuda_runtime.h>

#define N_NODES 50000
#define N_EDGES 600000
#define NFEAT   128
#define HIDDEN  64
#define NCLASS  40

// ---------------- scratch (static device globals; no allocs allowed) --------
__device__ float g_agg1[(size_t)N_NODES * NFEAT];   // 25.6 MB
__device__ float g_cnt [N_NODES];                   // in-degree (float)
__device__ float g_h   [(size_t)N_NODES * HIDDEN];  // 12.8 MB
__device__ float g_agg2[(size_t)N_NODES * HIDDEN];  // 12.8 MB
__device__ int   g_src[N_EDGES];
__device__ int   g_dst[N_EDGES];
__device__ int   g_is64;

// ---------------- edge dtype probe + convert ---------------------------------
// If the buffer really is int64, every reinterpreted value lies in [0, N_NODES).
// If it is int32, reinterpreting adjacent pairs as int64 gives values >= 2^32
// (upper word is a random nonzero index) -> flagged as 32-bit.
__global__ void detect_kernel(const void* ei_raw) {
    if (threadIdx.x == 0) {
        const long long* p = (const long long*)ei_raw;
        int ok64 = 1;
        for (int i = 0; i < 512; i++) {
            long long v = p[i];
            if (v < 0 || v >= N_NODES) { ok64 = 0; break; }
        }
        g_is64 = ok64;
    }
}

__global__ void convert_kernel(const void* ei_raw) {
    int i = blockIdx.x * blockDim.x + threadIdx.x;
    if (i >= N_EDGES) return;
    if (g_is64) {
        const long long* p = (const long long*)ei_raw;
        g_src[i] = (int)p[i];
        g_dst[i] = (int)p[N_EDGES + i];
    } else {
        const int* p = (const int*)ei_raw;
        g_src[i] = p[i];
        g_dst[i] = p[N_EDGES + i];
    }
}

// ---------------- zero scratch ----------------------------------------------
__global__ void zero_kernel() {
    size_t i = (size_t)blockIdx.x * blockDim.x + threadIdx.x;
    size_t stride = (size_t)gridDim.x * blockDim.x;
    for (size_t j = i; j < (size_t)N_NODES * NFEAT; j += stride) g_agg1[j] = 0.f;
    for (size_t j = i; j < (size_t)N_NODES;         j += stride) g_cnt[j]  = 0.f;
    for (size_t j = i; j < (size_t)N_NODES * HIDDEN;j += stride) g_agg2[j] = 0.f;
}

// ---------------- edge scatter, layer 1 (128 feats, 1 warp / edge) ---------
__global__ void scatter1_kernel(const float* __restrict__ x) {
    int gt = blockIdx.x * blockDim.x + threadIdx.x;
    int e = gt >> 5;
    if (e >= N_EDGES) return;
    int lane = gt & 31;
    int s = g_src[e];
    int d = g_dst[e];
    float4 v = ((const float4*)(x + (size_t)s * NFEAT))[lane];
    float* o = g_agg1 + (size_t)d * NFEAT + lane * 4;
    atomicAdd(o + 0, v.x);
    atomicAdd(o + 1, v.y);
    atomicAdd(o + 2, v.z);
    atomicAdd(o + 3, v.w);
    if (lane == 0) atomicAdd(&g_cnt[d], 1.0f);
}

// ---------------- edge scatter, layer 2 (64 feats, 16 lanes / edge) --------
__global__ void scatter2_kernel() {
    int gt = blockIdx.x * blockDim.x + threadIdx.x;
    int e = gt >> 4;
    if (e >= N_EDGES) return;
    int lane = gt & 15;
    int s = g_src[e];
    int d = g_dst[e];
    float4 v = ((const float4*)(g_h + (size_t)s * HIDDEN))[lane];
    float* o = g_agg2 + (size_t)d * HIDDEN + lane * 4;
    atomicAdd(o + 0, v.x);
    atomicAdd(o + 1, v.y);
    atomicAdd(o + 2, v.z);
    atomicAdd(o + 3, v.w);
}

// ---------------- layer 1: h = sigmoid([agg/cnt | x] @ [Wl1|Wr1]^T + bl1) --
// One GEMM with K=256, C=64. Block = 256 threads = 256 nodes.
#define L1_WPAD 72
__global__ __launch_bounds__(256) void layer1_kernel(
    const float* __restrict__ x, const float* __restrict__ Wl,
    const float* __restrict__ bl, const float* __restrict__ Wr) {
    extern __shared__ float sm[];
    float* sW = sm;                    // [256][72] : sW[k*72+c]
    float* sA = sm + 256 * L1_WPAD;    // [256][33] staged A chunk (32 k)
    __shared__ float sInv[256];

    int tid = threadIdx.x;
    for (int i = tid; i < 64 * 128; i += 256) {
        int c = i >> 7, k = i & 127;
        sW[k * L1_WPAD + c]         = Wl[i];
        sW[(k + 128) * L1_WPAD + c] = Wr[i];
    }
    int node = blockIdx.x * 256 + tid;
    float inv = 0.f;
    if (node < N_NODES) inv = 1.0f / fmaxf(g_cnt[node], 1.0f);
    sInv[tid] = inv;

    float4 acc[16];
#pragma unroll
    for (int i = 0; i < 16; i++) acc[i] = make_float4(0.f, 0.f, 0.f, 0.f);

    for (int kc = 0; kc < 256; kc += 32) {
        __syncthreads();
        for (int i = tid; i < 256 * 32; i += 256) {
            int nl = i >> 5, kk = i & 31;
            int gn = blockIdx.x * 256 + nl;
            float v = 0.f;
            if (gn < N_NODES) {
                int k = kc + kk;
                if (k < 128) v = g_agg1[(size_t)gn * NFEAT + k] * sInv[nl];
                else         v = x[(size_t)gn * NFEAT + (k - 128)];
            }
            sA[nl * 33 + kk] = v;
        }
        __syncthreads();
#pragma unroll 8
        for (int kk = 0; kk < 32; kk++) {
            float a = sA[tid * 33 + kk];
            const float4* w4 = (const float4*)(sW + (kc + kk) * L1_WPAD);
#pragma unroll
            for (int c = 0; c < 16; c++) {
                float4 w = w4[c];
                acc[c].x += a * w.x; acc[c].y += a * w.y;
                acc[c].z += a * w.z; acc[c].w += a * w.w;
            }
        }
    }

    if (node < N_NODES) {
        float4* ho = (float4*)(g_h + (size_t)node * HIDDEN);
#pragma unroll
        for (int c = 0; c < 16; c++) {
            float4 b = ((const float4*)bl)[c];
            float4 r;
            r.x = 1.0f / (1.0f + expf(-(acc[c].x + b.x)));
            r.y = 1.0f / (1.0f + expf(-(acc[c].y + b.y)));
            r.z = 1.0f / (1.0f + expf(-(acc[c].z + b.z)));
            r.w = 1.0f / (1.0f + expf(-(acc[c].w + b.w)));
            ho[c] = r;
        }
    }
}

// ---------------- layer 2: out = [agg2/cnt | h] @ [Wl2|Wr2]^T + bl2 --------
__global__ __launch_bounds__(256) void layer2_kernel(
    const float* __restrict__ Wl, const float* __restrict__ bl,
    const float* __restrict__ Wr, float* __restrict__ out) {
    extern __shared__ float sm[];
    float* sW = sm;                 // [128][40] : sW[k*40+c]
    float* sA = sm + 128 * 40;      // [256][33]
    __shared__ float sInv[256];

    int tid = threadIdx.x;
    for (int i = tid; i < 40 * 64; i += 256) {
        int c = i >> 6, k = i & 63;
        sW[k * 40 + c]        = Wl[i];
        sW[(k + 64) * 40 + c] = Wr[i];
    }
    int node = blockIdx.x * 256 + tid;
    float inv = 0.f;
    if (node < N_NODES) inv = 1.0f / fmaxf(g_cnt[node], 1.0f);
    sInv[tid] = inv;

    float4 acc[10];
#pragma unroll
    for (int i = 0; i < 10; i++) acc[i] = make_float4(0.f, 0.f, 0.f, 0.f);

    for (int kc = 0; kc < 128; kc += 32) {
        __syncthreads();
        for (int i = tid; i < 256 * 32; i += 256) {
            int nl = i >> 5, kk = i & 31;
            int gn = blockIdx.x * 256 + nl;
            float v = 0.f;
            if (gn < N_NODES) {
                int k = kc + kk;
                if (k < 64) v = g_agg2[(size_t)gn * HIDDEN + k] * sInv[nl];
                else        v = g_h[(size_t)gn * HIDDEN + (k - 64)];
            }
            sA[nl * 33 + kk] = v;
        }
        __syncthreads();
#pragma unroll 8
        for (int kk = 0; kk < 32; kk++) {
            float a = sA[tid * 33 + kk];
            const float4* w4 = (const float4*)(sW + (kc + kk) * 40);
#pragma unroll
            for (int c = 0; c < 10; c++) {
                float4 w = w4[c];
                acc[c].x += a * w.x; acc[c].y += a * w.y;
                acc[c].z += a * w.z; acc[c].w += a * w.w;
            }
        }
    }

    if (node < N_NODES) {
        float4* oo = (float4*)(out + (size_t)node * NCLASS);
#pragma unroll
        for (int c = 0; c < 10; c++) {
            float4 b = ((const float4*)bl)[c];
            float4 r;
            r.x = acc[c].x + b.x; r.y = acc[c].y + b.y;
            r.z = acc[c].z + b.z; r.w = acc[c].w + b.w;
            oo[c] = r;
        }
    }
}

// ---------------- launch ----------------------------------------------------
extern "C" void kernel_launch(void* const* d_in, const int* in_sizes, int n_in,
                              void* d_out, int out_size) {
    const float* x   = (const float*)d_in[0];
    const void*  ei  = d_in[1];
    const float* Wl1 = (const float*)d_in[2];
    const float* bl1 = (const float*)d_in[3];
    const float* Wr1 = (const float*)d_in[4];
    const float* Wl2 = (const float*)d_in[5];
    const float* bl2 = (const float*)d_in[6];
    const float* Wr2 = (const float*)d_in[7];
    float* out = (float*)d_out;

    const int l1_smem = (256 * L1_WPAD + 256 * 33) * sizeof(float);  // ~107 KB
    const int l2_smem = (128 * 40 + 256 * 33) * sizeof(float);       // ~54 KB
    cudaFuncSetAttribute(layer1_kernel, cudaFuncAttributeMaxDynamicSharedMemorySize, l1_smem);
    cudaFuncSetAttribute(layer2_kernel, cudaFuncAttributeMaxDynamicSharedMemorySize, l2_smem);

    detect_kernel<<<1, 32>>>(ei);
    convert_kernel<<<(N_EDGES + 255) / 256, 256>>>(ei);
    zero_kernel<<<512, 256>>>();
    scatter1_kernel<<<(N_EDGES * 32) / 256, 256>>>(x);
    const int nblocks = (N_NODES + 255) / 256;  // 196
    layer1_kernel<<<nblocks, 256, l1_smem>>>(x, Wl1, bl1, Wr1);
    scatter2_kernel<<<(N_EDGES * 16) / 256, 256>>>();
    layer2_kernel<<<nblocks, 256, l2_smem>>>(Wl2, bl2, Wr2, out);
}

// round 5
// speedup vs baseline: 1.7215x; 1.7215x over previous
#include <cuda_runtime.h>

#define N_NODES 50000
#define N_EDGES 600000
#define NFEAT   128
#define HIDDEN  64
#define NCLASS  40

// ---------------- scratch (static device globals; device-code access ONLY) --
__device__ int   g_src[N_EDGES];
__device__ int   g_dst[N_EDGES];
__device__ int   g_csr_src[N_EDGES];
__device__ int   g_deg[N_NODES];
__device__ int   g_rowptr[N_NODES];
__device__ int   g_cursor[N_NODES];
__device__ int   g_is64;

__device__ float g_y1[(size_t)N_NODES * HIDDEN];  // x @ Wl1^T
__device__ float g_z1[(size_t)N_NODES * HIDDEN];  // x @ Wr1^T
__device__ float g_h [(size_t)N_NODES * HIDDEN];  // layer-1 output
__device__ float g_y2[(size_t)N_NODES * NCLASS];  // h @ Wl2^T
__device__ float g_z2[(size_t)N_NODES * NCLASS];  // h @ Wr2^T

// ---------------- edge dtype probe ------------------------------------------
__global__ void detect_kernel(const void* ei_raw) {
    if (threadIdx.x == 0) {
        const long long* p = (const long long*)ei_raw;
        int ok64 = 1;
        for (int i = 0; i < 512; i++) {
            long long v = p[i];
            if (v < 0 || v >= N_NODES) { ok64 = 0; break; }
        }
        g_is64 = ok64;
    }
}

__global__ void zero_deg_kernel() {
    int i = blockIdx.x * blockDim.x + threadIdx.x;
    if (i < N_NODES) g_deg[i] = 0;
}

// convert edge dtype + histogram in-degree
__global__ void convert_kernel(const void* ei_raw) {
    int i = blockIdx.x * blockDim.x + threadIdx.x;
    if (i >= N_EDGES) return;
    int s, d;
    if (g_is64) {
        const long long* p = (const long long*)ei_raw;
        s = (int)p[i];
        d = (int)p[N_EDGES + i];
    } else {
        const int* p = (const int*)ei_raw;
        s = p[i];
        d = p[N_EDGES + i];
    }
    g_src[i] = s;
    g_dst[i] = d;
    atomicAdd(&g_deg[d], 1);
}

// ---------------- single-block exclusive scan of g_deg -> g_rowptr/g_cursor -
__global__ __launch_bounds__(1024) void scan_kernel() {
    __shared__ int warp_sums[32];
    __shared__ int s_carry;
    int tid = threadIdx.x, lane = tid & 31, wid = tid >> 5;
    if (tid == 0) s_carry = 0;
    __syncthreads();
    for (int base = 0; base < N_NODES; base += 1024) {
        int i = base + tid;
        int v = (i < N_NODES) ? g_deg[i] : 0;
        int inc = v;
#pragma unroll
        for (int off = 1; off < 32; off <<= 1) {
            int n = __shfl_up_sync(0xffffffffu, inc, off);
            if (lane >= off) inc += n;
        }
        if (lane == 31) warp_sums[wid] = inc;
        __syncthreads();
        if (wid == 0) {
            int ws = warp_sums[lane];
#pragma unroll
            for (int off = 1; off < 32; off <<= 1) {
                int n = __shfl_up_sync(0xffffffffu, ws, off);
                if (lane >= off) ws += n;
            }
            warp_sums[lane] = ws;
        }
        __syncthreads();
        int warp_prefix = (wid > 0) ? warp_sums[wid - 1] : 0;
        int excl = s_carry + warp_prefix + inc - v;
        if (i < N_NODES) { g_rowptr[i] = excl; g_cursor[i] = excl; }
        __syncthreads();
        if (tid == 1023) s_carry += warp_sums[31];
        __syncthreads();
    }
}

__global__ void fill_kernel() {
    int e = blockIdx.x * blockDim.x + threadIdx.x;
    if (e >= N_EDGES) return;
    int d = g_dst[e];
    int pos = atomicAdd(&g_cursor[d], 1);
    g_csr_src[pos] = g_src[e];
}

// ---------------- fused dual projection -------------------------------------
// y[n][c] = sum_k in[n][k]*Wl[c][k],  z[n][c] = sum_k in[n][k]*Wr[c][k]
// LAYER=1: in=x (param), y=g_y1, z=g_z1.  LAYER=2: in=g_h, y=g_y2, z=g_z2.
// Block = 256 threads = 256 nodes. Both W^T tiles live in smem; A staged once.
template<int K, int C, int LAYER>
__global__ __launch_bounds__(256) void gemm2_kernel(
    const float* __restrict__ in_param,
    const float* __restrict__ Wl, const float* __restrict__ Wr) {
    constexpr int CP = C + 8;          // float4-aligned pad (C % 8 == 0)
    extern __shared__ float sm[];
    float* sWl = sm;                   // [K][CP]
    float* sWr = sm + K * CP;          // [K][CP]
    float* sA  = sm + 2 * K * CP;      // [256][33]

    const float* in = (LAYER == 1) ? in_param : g_h;
    float* y = (LAYER == 1) ? g_y1 : g_y2;
    float* z = (LAYER == 1) ? g_z1 : g_z2;

    int tid = threadIdx.x;
    for (int i = tid; i < C * K; i += 256) {
        int c = i / K, k = i % K;      // W row-major [C][K]
        sWl[k * CP + c] = Wl[i];
        sWr[k * CP + c] = Wr[i];
    }
    int node = blockIdx.x * 256 + tid;

    float4 accY[C / 4], accZ[C / 4];
#pragma unroll
    for (int i = 0; i < C / 4; i++) {
        accY[i] = make_float4(0.f, 0.f, 0.f, 0.f);
        accZ[i] = make_float4(0.f, 0.f, 0.f, 0.f);
    }

    for (int kc = 0; kc < K; kc += 32) {
        __syncthreads();
        for (int i = tid; i < 256 * 32; i += 256) {
            int nl = i >> 5, kk = i & 31;
            int gn = blockIdx.x * 256 + nl;
            sA[nl * 33 + kk] = (gn < N_NODES) ? in[(size_t)gn * K + kc + kk] : 0.f;
        }
        __syncthreads();
#pragma unroll 4
        for (int kk = 0; kk < 32; kk++) {
            float a = sA[tid * 33 + kk];
            const float4* wl4 = (const float4*)(sWl + (kc + kk) * CP);
            const float4* wr4 = (const float4*)(sWr + (kc + kk) * CP);
#pragma unroll
            for (int c = 0; c < C / 4; c++) {
                float4 wl = wl4[c], wr = wr4[c];
                accY[c].x += a * wl.x; accY[c].y += a * wl.y;
                accY[c].z += a * wl.z; accY[c].w += a * wl.w;
                accZ[c].x += a * wr.x; accZ[c].y += a * wr.y;
                accZ[c].z += a * wr.z; accZ[c].w += a * wr.w;
            }
        }
    }

    if (node < N_NODES) {
        float4* oy = (float4*)(y + (size_t)node * C);
        float4* oz = (float4*)(z + (size_t)node * C);
#pragma unroll
        for (int c = 0; c < C / 4; c++) { oy[c] = accY[c]; oz[c] = accZ[c]; }
    }
}

// ---------------- agg1: h = sigmoid(mean(y1[src]) + z1 + bl1) ---------------
// One warp per node; each lane owns 2 of the 64 features (float2).
__global__ __launch_bounds__(256) void agg1_kernel(const float* __restrict__ bl) {
    int gw = (blockIdx.x * 256 + threadIdx.x) >> 5;
    if (gw >= N_NODES) return;
    int lane = threadIdx.x & 31;
    int start = g_rowptr[gw], deg = g_deg[gw], end = start + deg;
    float ax = 0.f, ay = 0.f;
    for (int e = start; e < end; e++) {
        int s = g_csr_src[e];
        float2 v = ((const float2*)(g_y1 + (size_t)s * HIDDEN))[lane];
        ax += v.x; ay += v.y;
    }
    float inv = 1.f / fmaxf((float)deg, 1.f);
    float2 zv = ((const float2*)(g_z1 + (size_t)gw * HIDDEN))[lane];
    float b0 = bl[lane * 2], b1 = bl[lane * 2 + 1];
    float2 r;
    r.x = 1.f / (1.f + expf(-(ax * inv + zv.x + b0)));
    r.y = 1.f / (1.f + expf(-(ay * inv + zv.y + b1)));
    ((float2*)(g_h + (size_t)gw * HIDDEN))[lane] = r;
}

// ---------------- agg2: out = mean(y2[src]) + z2 + bl2 ----------------------
// One warp per node; lane owns feature `lane`, lanes 0..7 also own 32+lane.
__global__ __launch_bounds__(256) void agg2_kernel(const float* __restrict__ bl,
                                                   float* __restrict__ out) {
    int gw = (blockIdx.x * 256 + threadIdx.x) >> 5;
    if (gw >= N_NODES) return;
    int lane = threadIdx.x & 31;
    int start = g_rowptr[gw], deg = g_deg[gw], end = start + deg;
    float a0 = 0.f, a1 = 0.f;
    for (int e = start; e < end; e++) {
        int s = g_csr_src[e];
        const float* r = g_y2 + (size_t)s * NCLASS;
        a0 += r[lane];
        if (lane < 8) a1 += r[32 + lane];
    }
    float inv = 1.f / fmaxf((float)deg, 1.f);
    const float* zr = g_z2 + (size_t)gw * NCLASS;
    float* o = out + (size_t)gw * NCLASS;
    o[lane] = a0 * inv + zr[lane] + bl[lane];
    if (lane < 8) o[32 + lane] = a1 * inv + zr[32 + lane] + bl[32 + lane];
}

// ---------------- launch ----------------------------------------------------
extern "C" void kernel_launch(void* const* d_in, const int* in_sizes, int n_in,
                              void* d_out, int out_size) {
    const float* x   = (const float*)d_in[0];
    const void*  ei  = d_in[1];
    const float* Wl1 = (const float*)d_in[2];
    const float* bl1 = (const float*)d_in[3];
    const float* Wr1 = (const float*)d_in[4];
    const float* Wl2 = (const float*)d_in[5];
    const float* bl2 = (const float*)d_in[6];
    const float* Wr2 = (const float*)d_in[7];
    float* out = (float*)d_out;

    // layer1: 2*128*72 + 256*33 floats = 26880 fl = 107,520 B
    // layer2: 2*64*48  + 256*33 floats = 14592 fl =  58,368 B
    const int g1_smem = (2 * NFEAT * (HIDDEN + 8) + 256 * 33) * (int)sizeof(float);
    const int g2_smem = (2 * HIDDEN * (NCLASS + 8) + 256 * 33) * (int)sizeof(float);
    cudaFuncSetAttribute(gemm2_kernel<NFEAT, HIDDEN, 1>,
                         cudaFuncAttributeMaxDynamicSharedMemorySize, g1_smem);
    cudaFuncSetAttribute(gemm2_kernel<HIDDEN, NCLASS, 2>,
                         cudaFuncAttributeMaxDynamicSharedMemorySize, g2_smem);

    const int eblocks = (N_EDGES + 255) / 256;
    const int nblocks = (N_NODES + 255) / 256;       // 196
    const int wblocks = (N_NODES * 32 + 255) / 256;  // 6250

    detect_kernel<<<1, 32>>>(ei);
    zero_deg_kernel<<<nblocks, 256>>>();
    convert_kernel<<<eblocks, 256>>>(ei);
    scan_kernel<<<1, 1024>>>();
    fill_kernel<<<eblocks, 256>>>();

    gemm2_kernel<NFEAT, HIDDEN, 1><<<nblocks, 256, g1_smem>>>(x, Wl1, Wr1);
    agg1_kernel<<<wblocks, 256>>>(bl1);
    gemm2_kernel<HIDDEN, NCLASS, 2><<<nblocks, 256, g2_smem>>>(nullptr, Wl2, Wr2);
    agg2_kernel<<<wblocks, 256>>>(bl2, out);
}

// round 6
// speedup vs baseline: 1.8176x; 1.0558x over previous
#include <cuda_runtime.h>

#define N_NODES 50000
#define N_EDGES 600000
#define NFEAT   128
#define HIDDEN  64
#define NCLASS  40

// packed fp32x2 FMA (FFMA2): d = a*b + d per 32-bit half
#define FMA_X2(acc, a, w) \
    asm("fma.rn.f32x2 %0, %1, %2, %0;" : "+l"(acc) : "l"(a), "l"(w))
#define UNPK(lo, hi, p) \
    asm("mov.b64 {%0, %1}, %2;" : "=f"(lo), "=f"(hi) : "l"(p))

// ---------------- scratch (static device globals; device-code access ONLY) --
__device__ int   g_src[N_EDGES];
__device__ int   g_dst[N_EDGES];
__device__ int   g_csr_src[N_EDGES];
__device__ int   g_deg[N_NODES];
__device__ int   g_rowptr[N_NODES];
__device__ int   g_cursor[N_NODES];
__device__ int   g_is64;

__device__ float g_y1[(size_t)N_NODES * HIDDEN];  // x @ Wl1^T
__device__ float g_z1[(size_t)N_NODES * HIDDEN];  // x @ Wr1^T
__device__ float g_h [(size_t)N_NODES * HIDDEN];  // layer-1 output
__device__ float g_y2[(size_t)N_NODES * NCLASS];  // h @ Wl2^T
__device__ float g_z2[(size_t)N_NODES * NCLASS];  // h @ Wr2^T

// ---------------- init: zero degrees + edge dtype probe ----------------------
// int64 buffer: every reinterpreted value in [0, N_NODES). int32 buffer read
// as int64 fuses two random indices -> almost surely out of range.
__global__ void init_kernel(const void* ei_raw) {
    int i = blockIdx.x * blockDim.x + threadIdx.x;
    if (i < N_NODES) g_deg[i] = 0;
    if (i == 0) {
        const long long* p = (const long long*)ei_raw;
        int ok64 = 1;
#pragma unroll 8
        for (int j = 0; j < 64; j++) {
            long long v = p[j];
            if (v < 0 || v >= N_NODES) ok64 = 0;
        }
        g_is64 = ok64;
    }
}

// convert edge dtype + histogram in-degree
__global__ void convert_kernel(const void* ei_raw) {
    int i = blockIdx.x * blockDim.x + threadIdx.x;
    if (i >= N_EDGES) return;
    int s, d;
    if (g_is64) {
        const long long* p = (const long long*)ei_raw;
        s = (int)p[i];
        d = (int)p[N_EDGES + i];
    } else {
        const int* p = (const int*)ei_raw;
        s = p[i];
        d = p[N_EDGES + i];
    }
    g_src[i] = s;
    g_dst[i] = d;
    atomicAdd(&g_deg[d], 1);
}

// ---------------- single-block chunked exclusive scan ------------------------
// Each thread owns 13 int4 (52 ints); one block-scan of thread sums; 2 barriers.
// N_NODES % 4 == 0 (12500 int4 total).
__global__ __launch_bounds__(1024) void scan_kernel() {
    constexpr int CH4 = 13;                 // int4 per thread (1024*13*4 >= 50000)
    constexpr int N4 = N_NODES / 4;         // 12500
    int tid = threadIdx.x, lane = tid & 31, wid = tid >> 5;
    const int4* deg4 = (const int4*)g_deg;

    int s = 0;
#pragma unroll
    for (int j = 0; j < CH4; j++) {
        int i4 = tid * CH4 + j;
        if (i4 < N4) {
            int4 v = deg4[i4];
            s += v.x + v.y + v.z + v.w;
        }
    }
    // block scan of per-thread sums
    __shared__ int wsum[32];
    int inc = s;
#pragma unroll
    for (int off = 1; off < 32; off <<= 1) {
        int n = __shfl_up_sync(0xffffffffu, inc, off);
        if (lane >= off) inc += n;
    }
    if (lane == 31) wsum[wid] = inc;
    __syncthreads();
    if (wid == 0) {
        int ws = wsum[lane];
#pragma unroll
        for (int off = 1; off < 32; off <<= 1) {
            int n = __shfl_up_sync(0xffffffffu, ws, off);
            if (lane >= off) ws += n;
        }
        wsum[lane] = ws;
    }
    __syncthreads();
    int excl = (wid > 0 ? wsum[wid - 1] : 0) + inc - s;

    int4* rp4 = (int4*)g_rowptr;
    int4* cu4 = (int4*)g_cursor;
#pragma unroll
    for (int j = 0; j < CH4; j++) {
        int i4 = tid * CH4 + j;
        if (i4 < N4) {
            int4 v = deg4[i4];
            int4 p;
            p.x = excl;
            p.y = p.x + v.x;
            p.z = p.y + v.y;
            p.w = p.z + v.z;
            excl = p.w + v.w;
            rp4[i4] = p;
            cu4[i4] = p;
        }
    }
}

__global__ void fill_kernel() {
    int e = blockIdx.x * blockDim.x + threadIdx.x;
    if (e >= N_EDGES) return;
    int d = g_dst[e];
    int pos = atomicAdd(&g_cursor[d], 1);
    g_csr_src[pos] = g_src[e];
}

// ---------------- fused dual projection (FFMA2) ------------------------------
// y[n][c] = sum_k in[n][k]*Wl[c][k],  z[n][c] = sum_k in[n][k]*Wr[c][k]
// LAYER=1: in=x (param), y=g_y1, z=g_z1.  LAYER=2: in=g_h, y=g_y2, z=g_z2.
// Block = 256 threads = 256 nodes. Accumulators are packed fp32 pairs.
template<int K, int C, int LAYER>
__global__ __launch_bounds__(256) void gemm2_kernel(
    const float* __restrict__ in_param,
    const float* __restrict__ Wl, const float* __restrict__ Wr) {
    constexpr int CP = C + 8;          // pad, 16B-aligned rows (C%8==0)
    extern __shared__ float sm[];
    float* sWl = sm;                   // [K][CP]
    float* sWr = sm + K * CP;          // [K][CP]
    float* sA  = sm + 2 * K * CP;      // [256][33]

    const float* in = (LAYER == 1) ? in_param : g_h;
    float* y = (LAYER == 1) ? g_y1 : g_y2;
    float* z = (LAYER == 1) ? g_z1 : g_z2;

    int tid = threadIdx.x;
    for (int i = tid; i < C * K; i += 256) {
        int c = i / K, k = i % K;      // W row-major [C][K]
        sWl[k * CP + c] = Wl[i];
        sWr[k * CP + c] = Wr[i];
    }
    int node = blockIdx.x * 256 + tid;

    unsigned long long accY[C / 2], accZ[C / 2];
#pragma unroll
    for (int i = 0; i < C / 2; i++) { accY[i] = 0ull; accZ[i] = 0ull; }

    for (int kc = 0; kc < K; kc += 32) {
        __syncthreads();
        for (int i = tid; i < 256 * 32; i += 256) {
            int nl = i >> 5, kk = i & 31;
            int gn = blockIdx.x * 256 + nl;
            sA[nl * 33 + kk] = (gn < N_NODES) ? in[(size_t)gn * K + kc + kk] : 0.f;
        }
        __syncthreads();
#pragma unroll 4
        for (int kk = 0; kk < 32; kk++) {
            float a = sA[tid * 33 + kk];
            unsigned long long av;
            asm("mov.b64 %0, {%1, %1};" : "=l"(av) : "f"(a));
            const ulonglong2* wl4 = (const ulonglong2*)(sWl + (kc + kk) * CP);
            const ulonglong2* wr4 = (const ulonglong2*)(sWr + (kc + kk) * CP);
#pragma unroll
            for (int c = 0; c < C / 4; c++) {
                ulonglong2 wl = wl4[c], wr = wr4[c];
                FMA_X2(accY[2 * c],     av, wl.x);
                FMA_X2(accY[2 * c + 1], av, wl.y);
                FMA_X2(accZ[2 * c],     av, wr.x);
                FMA_X2(accZ[2 * c + 1], av, wr.y);
            }
        }
    }

    if (node < N_NODES) {
        float4* oy = (float4*)(y + (size_t)node * C);
        float4* oz = (float4*)(z + (size_t)node * C);
#pragma unroll
        for (int c = 0; c < C / 4; c++) {
            float4 vy, vz;
            UNPK(vy.x, vy.y, accY[2 * c]); UNPK(vy.z, vy.w, accY[2 * c + 1]);
            UNPK(vz.x, vz.y, accZ[2 * c]); UNPK(vz.z, vz.w, accZ[2 * c + 1]);
            oy[c] = vy; oz[c] = vz;
        }
    }
}

// ---------------- agg1: h = sigmoid(mean(y1[src]) + z1 + bl1) ---------------
// One warp per node; each lane owns 2 of the 64 features (float2).
__global__ __launch_bounds__(256) void agg1_kernel(const float* __restrict__ bl) {
    int gw = (blockIdx.x * 256 + threadIdx.x) >> 5;
    if (gw >= N_NODES) return;
    int lane = threadIdx.x & 31;
    int start = g_rowptr[gw], deg = g_deg[gw], end = start + deg;
    float ax = 0.f, ay = 0.f;
    for (int e = start; e < end; e++) {
        int s = g_csr_src[e];
        float2 v = ((const float2*)(g_y1 + (size_t)s * HIDDEN))[lane];
        ax += v.x; ay += v.y;
    }
    float inv = 1.f / fmaxf((float)deg, 1.f);
    float2 zv = ((const float2*)(g_z1 + (size_t)gw * HIDDEN))[lane];
    float b0 = bl[lane * 2], b1 = bl[lane * 2 + 1];
    float2 r;
    r.x = 1.f / (1.f + __expf(-(ax * inv + zv.x + b0)));
    r.y = 1.f / (1.f + __expf(-(ay * inv + zv.y + b1)));
    ((float2*)(g_h + (size_t)gw * HIDDEN))[lane] = r;
}

// ---------------- agg2: out = mean(y2[src]) + z2 + bl2 ----------------------
__global__ __launch_bounds__(256) void agg2_kernel(const float* __restrict__ bl,
                                                   float* __restrict__ out) {
    int gw = (blockIdx.x * 256 + threadIdx.x) >> 5;
    if (gw >= N_NODES) return;
    int lane = threadIdx.x & 31;
    int start = g_rowptr[gw], deg = g_deg[gw], end = start + deg;
    float a0 = 0.f, a1 = 0.f;
    for (int e = start; e < end; e++) {
        int s = g_csr_src[e];
        const float* r = g_y2 + (size_t)s * NCLASS;
        a0 += r[lane];
        if (lane < 8) a1 += r[32 + lane];
    }
    float inv = 1.f / fmaxf((float)deg, 1.f);
    const float* zr = g_z2 + (size_t)gw * NCLASS;
    float* o = out + (size_t)gw * NCLASS;
    o[lane] = a0 * inv + zr[lane] + bl[lane];
    if (lane < 8) o[32 + lane] = a1 * inv + zr[32 + lane] + bl[32 + lane];
}

// ---------------- launch ----------------------------------------------------
extern "C" void kernel_launch(void* const* d_in, const int* in_sizes, int n_in,
                              void* d_out, int out_size) {
    const float* x   = (const float*)d_in[0];
    const void*  ei  = d_in[1];
    const float* Wl1 = (const float*)d_in[2];
    const float* bl1 = (const float*)d_in[3];
    const float* Wr1 = (const float*)d_in[4];
    const float* Wl2 = (const float*)d_in[5];
    const float* bl2 = (const float*)d_in[6];
    const float* Wr2 = (const float*)d_in[7];
    float* out = (float*)d_out;

    const int g1_smem = (2 * NFEAT * (HIDDEN + 8) + 256 * 33) * (int)sizeof(float);
    const int g2_smem = (2 * HIDDEN * (NCLASS + 8) + 256 * 33) * (int)sizeof(float);
    cudaFuncSetAttribute(gemm2_kernel<NFEAT, HIDDEN, 1>,
                         cudaFuncAttributeMaxDynamicSharedMemorySize, g1_smem);
    cudaFuncSetAttribute(gemm2_kernel<HIDDEN, NCLASS, 2>,
                         cudaFuncAttributeMaxDynamicSharedMemorySize, g2_smem);

    const int eblocks = (N_EDGES + 255) / 256;
    const int nblocks = (N_NODES + 255) / 256;       // 196
    const int wblocks = (N_NODES * 32 + 255) / 256;  // 6250

    init_kernel<<<nblocks, 256>>>(ei);
    convert_kernel<<<eblocks, 256>>>(ei);
    scan_kernel<<<1, 1024>>>();
    fill_kernel<<<eblocks, 256>>>();

    gemm2_kernel<NFEAT, HIDDEN, 1><<<nblocks, 256, g1_smem>>>(x, Wl1, Wr1);
    agg1_kernel<<<wblocks, 256>>>(bl1);
    gemm2_kernel<HIDDEN, NCLASS, 2><<<nblocks, 256, g2_smem>>>(nullptr, Wl2, Wr2);
    agg2_kernel<<<wblocks, 256>>>(bl2, out);
}